// round 4
// baseline (speedup 1.0000x reference)
#include <cuda_runtime.h>
#include <cuda_bf16.h>

#define BB 4
#define C 128
#define H 128
#define W 128
#define HW (H*W)
#define ROWS 2

// Scratch (allocations are forbidden; __device__ globals are the sanctioned path)
__device__ float g_U[(size_t)BB*C*HW];   // 32 MB: u = x . M, layout [b][oc][p]
__device__ float g_A[BB*HW];             // alpha = v1 . x
__device__ float g_T[BB*HW];             // t     = v2 . x
__device__ float g_M[C*C];               // M[i][j] = sum_oc qw[oc][i]*kw[oc][j]
__device__ float g_v1[C];
__device__ float g_v2[C];
__device__ float g_gamma[1];

typedef unsigned long long ull;

__device__ __forceinline__ ull pack2(float v){
    ull r; unsigned u = __float_as_uint(v);
    asm("mov.b64 %0, {%1, %1};" : "=l"(r) : "r"(u));
    return r;
}
__device__ __forceinline__ void fma2(ull& d, ull a, ull b){
    asm("fma.rn.f32x2 %0, %1, %2, %0;" : "+l"(d) : "l"(a), "l"(b));
}

// ---------------------------------------------------------------------------
// Precompute M = Wq^T Wk, v1 = Wq^T b_k, v2 = Wk^T b_q, gamma = b_q . b_k
// ---------------------------------------------------------------------------
__global__ void precomp_kernel(const float* __restrict__ qw, const float* __restrict__ qb,
                               const float* __restrict__ kw, const float* __restrict__ kb){
    int idx = blockIdx.x * 256 + threadIdx.x;
    if (idx < C*C){
        int i = idx >> 7, j = idx & 127;
        float acc = 0.f;
        #pragma unroll 8
        for (int oc = 0; oc < C; oc++)
            acc = fmaf(__ldg(qw + oc*C + i), __ldg(kw + oc*C + j), acc);
        g_M[idx] = acc;
    } else if (idx < C*C + C){
        int i = idx - C*C;
        float acc = 0.f;
        #pragma unroll 8
        for (int oc = 0; oc < C; oc++)
            acc = fmaf(__ldg(qw + oc*C + i), __ldg(kb + oc), acc);
        g_v1[i] = acc;
    } else if (idx < C*C + 2*C){
        int j = idx - C*C - C;
        float acc = 0.f;
        #pragma unroll 8
        for (int oc = 0; oc < C; oc++)
            acc = fmaf(__ldg(qb + oc), __ldg(kw + oc*C + j), acc);
        g_v2[j] = acc;
    } else if (idx == C*C + 2*C){
        float acc = 0.f;
        for (int oc = 0; oc < C; oc++)
            acc = fmaf(qb[oc], kb[oc], acc);
        g_gamma[0] = acc;
    }
}

// ---------------------------------------------------------------------------
// Projection GEMM: u[b][oc][p] = sum_ic x[b][ic][p] * M[ic][oc]
// One CTA: 128 output channels x 128 pixels, full K=128 in smem (no k-pipe).
// Inner loop: packed f32x2 FMAs (pixel pairs), A broadcast amortized 4x.
// Also emits per-pixel alpha/t maps from the resident X tile.
// ---------------------------------------------------------------------------
__global__ __launch_bounds__(256) void proj_kernel(const float* __restrict__ feat){
    extern __shared__ float sm[];
    float* Ms = sm;            // [ic][oc], oc contiguous (16384 floats)
    float* Xs = sm + C*C;      // [ic][px], px contiguous (16384 floats)

    const int tid = threadIdx.x;
    const int b   = blockIdx.y;
    const int px0 = blockIdx.x * 128;

    {
        const float4* msrc = (const float4*)g_M;
        float4* mdst = (float4*)Ms;
        for (int e = tid; e < C*C/4; e += 256) mdst[e] = msrc[e];
        for (int e = tid; e < C*128/4; e += 256){
            int ic = e >> 5, p4 = e & 31;
            ((float4*)Xs)[ic*32 + p4] =
                ((const float4*)(feat + ((size_t)(b*C + ic))*HW + px0))[p4];
        }
    }
    __syncthreads();

    const int ty = tid >> 4, tx = tid & 15;
    const int oc0 = ty * 8, pl0 = tx * 8;

    ull acc[8][4];
    #pragma unroll
    for (int i = 0; i < 8; i++)
        #pragma unroll
        for (int j = 0; j < 4; j++) acc[i][j] = 0ull;

    #pragma unroll 4
    for (int ic = 0; ic < C; ic++){
        const float* Ar = Ms + ic*C + oc0;
        const ull*   Br = (const ull*)(Xs + ic*128 + pl0);
        float4 a0 = *(const float4*)Ar;
        float4 a1 = *(const float4*)(Ar + 4);
        ull b0 = Br[0], b1 = Br[1], b2 = Br[2], b3 = Br[3];
        float av[8] = {a0.x, a0.y, a0.z, a0.w, a1.x, a1.y, a1.z, a1.w};
        #pragma unroll
        for (int i = 0; i < 8; i++){
            ull a2 = pack2(av[i]);
            fma2(acc[i][0], a2, b0);
            fma2(acc[i][1], a2, b1);
            fma2(acc[i][2], a2, b2);
            fma2(acc[i][3], a2, b3);
        }
    }

    #pragma unroll
    for (int i = 0; i < 8; i++){
        ull* urow = (ull*)(g_U + ((size_t)(b*C + oc0 + i))*HW + px0 + pl0);
        #pragma unroll
        for (int j = 0; j < 4; j++) urow[j] = acc[i][j];
    }

    // alpha / t maps for this CTA's 128 pixels (X tile still resident)
    if (tid < 128){
        float a = 0.f, t = 0.f;
        #pragma unroll 8
        for (int ic = 0; ic < C; ic++){
            float xv = Xs[ic*128 + tid];
            a = fmaf(xv, g_v1[ic], a);
            t = fmaf(xv, g_v2[ic], t);
        }
        g_A[b*HW + px0 + tid] = a;
        g_T[b*HW + px0 + tid] = t;
    }
}

// ---------------------------------------------------------------------------
// Local-window attention: scores_n = (u.x_n + alpha + t_n + gamma)/sqrt(C),
// OOB neighbors get score EXACTLY 0 (reference zero-pads the k-map),
// softmax over 9, then weighted flow gather (OOB flow contributes 0).
// CTA = 2 rows x 128 cols; feature halo staged in smem 8 channels at a time.
// ---------------------------------------------------------------------------
__global__ __launch_bounds__(256) void attn_kernel(const float* __restrict__ feat,
                                                   const float* __restrict__ flow,
                                                   float* __restrict__ out){
    __shared__ float sK[8][ROWS+2][W+4];
    __shared__ float sT[ROWS+2][W+4];

    const int tid = threadIdx.x;
    const int b = blockIdx.y;
    const int rowBase = blockIdx.x * ROWS;
    const int r = tid >> 7;
    const int x = tid & 127;
    const int y = rowBase + r;
    const int p = y*W + x;

    const float* ub = g_U + (size_t)b*C*HW + p;
    const float* fb = feat + (size_t)b*C*HW;

    float s[9];
    #pragma unroll
    for (int n = 0; n < 9; n++) s[n] = 0.f;

    for (int cb = 0; cb < C; cb += 8){
        for (int e = tid; e < 8*(ROWS+2)*130; e += 256){
            int c   = e / ((ROWS+2)*130);
            int rem = e - c*((ROWS+2)*130);
            int row = rem / 130;
            int col = rem - row*130;
            int gy = rowBase - 1 + row;
            int gx = col - 1;
            float v = 0.f;
            if ((unsigned)gy < (unsigned)H && (unsigned)gx < (unsigned)W)
                v = fb[(size_t)(cb + c)*HW + gy*W + gx];
            sK[c][row][col] = v;
        }
        __syncthreads();
        #pragma unroll
        for (int cc = 0; cc < 8; cc++){
            float uv = ub[(size_t)(cb + cc)*HW];
            #pragma unroll
            for (int dy = 0; dy < 3; dy++)
                #pragma unroll
                for (int dx = 0; dx < 3; dx++)
                    s[dy*3+dx] = fmaf(uv, sK[cc][r+dy][x+dx], s[dy*3+dx]);
        }
        __syncthreads();
    }

    // stage t-map halo
    for (int e = tid; e < (ROWS+2)*130; e += 256){
        int row = e / 130, col = e - row*130;
        int gy = rowBase - 1 + row, gx = col - 1;
        float v = 0.f;
        if ((unsigned)gy < (unsigned)H && (unsigned)gx < (unsigned)W)
            v = g_T[b*HW + gy*W + gx];
        sT[row][col] = v;
    }
    __syncthreads();

    const float alpha = g_A[b*HW + p];
    const float gam = g_gamma[0];
    const float INV = 0.08838834764831843f;   // 1/sqrt(128)

    float sc[9];
    #pragma unroll
    for (int dy = 0; dy < 3; dy++)
        #pragma unroll
        for (int dx = 0; dx < 3; dx++){
            int n = dy*3+dx;
            bool inb = ((unsigned)(y+dy-1) < (unsigned)H) &&
                       ((unsigned)(x+dx-1) < (unsigned)W);
            sc[n] = inb ? (s[n] + alpha + sT[r+dy][x+dx] + gam) * INV : 0.f;
        }

    float m = sc[0];
    #pragma unroll
    for (int n = 1; n < 9; n++) m = fmaxf(m, sc[n]);
    float es[9], sum = 0.f;
    #pragma unroll
    for (int n = 0; n < 9; n++){ es[n] = __expf(sc[n] - m); sum += es[n]; }
    const float isum = 1.f / sum;

    const float* fl0 = flow + (size_t)(b*2)*HW;
    const float* fl1 = fl0 + HW;
    float f0 = 0.f, f1 = 0.f;
    #pragma unroll
    for (int dy = 0; dy < 3; dy++)
        #pragma unroll
        for (int dx = 0; dx < 3; dx++){
            int n = dy*3+dx;
            int gy = y + dy - 1, gx = x + dx - 1;
            if ((unsigned)gy < (unsigned)H && (unsigned)gx < (unsigned)W){
                int pn = gy*W + gx;
                float pr = es[n] * isum;
                f0 = fmaf(pr, fl0[pn], f0);
                f1 = fmaf(pr, fl1[pn], f1);
            }
        }
    out[(size_t)(b*2)*HW + p]     = f0;
    out[(size_t)(b*2+1)*HW + p]   = f1;
}

extern "C" void kernel_launch(void* const* d_in, const int* in_sizes, int n_in,
                              void* d_out, int out_size){
    const float* feature0 = (const float*)d_in[0];
    const float* flow     = (const float*)d_in[1];
    const float* q_w      = (const float*)d_in[2];
    const float* q_b      = (const float*)d_in[3];
    const float* k_w      = (const float*)d_in[4];
    const float* k_b      = (const float*)d_in[5];
    float* out = (float*)d_out;
    (void)in_sizes; (void)n_in; (void)out_size;

    precomp_kernel<<<(C*C + 2*C + 1 + 255)/256, 256>>>(q_w, q_b, k_w, k_b);

    const int smem_bytes = 2 * C * C * sizeof(float);  // 128 KB
    cudaFuncSetAttribute(proj_kernel, cudaFuncAttributeMaxDynamicSharedMemorySize, smem_bytes);
    proj_kernel<<<dim3(HW/128, BB), 256, smem_bytes>>>(feature0);

    attn_kernel<<<dim3(H/ROWS, BB), 256>>>(feature0, flow, out);
}

// round 6
// speedup vs baseline: 1.3772x; 1.3772x over previous
#include <cuda_runtime.h>
#include <cuda_bf16.h>
#include <cstdint>

#define BB 4
#define C 128
#define H 128
#define W 128
#define HW (H*W)
#define ROWS 2

typedef unsigned long long ull;

// ------------------------- device scratch (no allocs) -----------------------
__device__ float          g_U[(size_t)BB*C*HW];  // u' = x.M + v2, layout [b][oc][px]
__device__ unsigned short g_Mhi[C*C];            // M^T hi, plain bf16 [oc][ic]
__device__ unsigned short g_Mlo[C*C];            // M^T lo
__device__ float          g_v1[C];
__device__ float          g_v2[C];
__device__ float          g_gamma[1];

__device__ __forceinline__ uint32_t smem_u32(const void* p){
    uint32_t a;
    asm("{ .reg .u64 t; cvta.to.shared.u64 t, %1; cvt.u32.u64 %0, t; }" : "=r"(a) : "l"(p));
    return a;
}
__device__ __forceinline__ void ldm_x4(uint32_t addr, uint32_t& r0, uint32_t& r1,
                                       uint32_t& r2, uint32_t& r3){
    asm volatile("ldmatrix.sync.aligned.m8n8.x4.shared.b16 {%0,%1,%2,%3}, [%4];"
        : "=r"(r0), "=r"(r1), "=r"(r2), "=r"(r3) : "r"(addr));
}
__device__ __forceinline__ void mma_bf16(float* d, const uint32_t* a, const uint32_t* b){
    asm volatile("mma.sync.aligned.m16n8k16.row.col.f32.bf16.bf16.f32 "
        "{%0,%1,%2,%3}, {%4,%5,%6,%7}, {%8,%9}, {%0,%1,%2,%3};"
        : "+f"(d[0]), "+f"(d[1]), "+f"(d[2]), "+f"(d[3])
        : "r"(a[0]), "r"(a[1]), "r"(a[2]), "r"(a[3]), "r"(b[0]), "r"(b[1]));
}
__device__ __forceinline__ void split_bf16(float v, unsigned short& h, unsigned short& l){
    __nv_bfloat16 bh = __float2bfloat16(v);
    float r = v - __bfloat162float(bh);
    __nv_bfloat16 bl = __float2bfloat16(r);
    h = __bfloat16_as_ushort(bh);
    l = __bfloat16_as_ushort(bl);
}

// ---------------------------------------------------------------------------
// precomp: M^T[oc][ic] = sum_t qw[t][ic]*kw[t][oc]  (bf16 hi/lo),
// v1 = Wq^T b_k, v2 = Wk^T b_q, gamma = b_q.b_k
// ---------------------------------------------------------------------------
__global__ __launch_bounds__(256) void precomp_kernel(const float* __restrict__ qw,
                                                      const float* __restrict__ qb,
                                                      const float* __restrict__ kw,
                                                      const float* __restrict__ kb){
    const int ci = blockIdx.x;
    const int t  = threadIdx.x;
    if (ci < 16){
        const int oc  = ci * 8 + (t >> 5);
        const int ic0 = (t & 31) * 4;
        float a0 = 0.f, a1 = 0.f, a2 = 0.f, a3 = 0.f;
        #pragma unroll 4
        for (int k = 0; k < C; k++){
            float4 q4 = __ldg((const float4*)(qw + k * C + ic0));
            float kv = __ldg(kw + k * C + oc);
            a0 = fmaf(q4.x, kv, a0);
            a1 = fmaf(q4.y, kv, a1);
            a2 = fmaf(q4.z, kv, a2);
            a3 = fmaf(q4.w, kv, a3);
        }
        unsigned short h0,h1,h2,h3,l0,l1,l2,l3;
        split_bf16(a0,h0,l0); split_bf16(a1,h1,l1);
        split_bf16(a2,h2,l2); split_bf16(a3,h3,l3);
        ull hi = (ull)h0 | ((ull)h1<<16) | ((ull)h2<<32) | ((ull)h3<<48);
        ull lo = (ull)l0 | ((ull)l1<<16) | ((ull)l2<<32) | ((ull)l3<<48);
        *(ull*)(g_Mhi + oc*C + ic0) = hi;
        *(ull*)(g_Mlo + oc*C + ic0) = lo;
    } else {
        if (t < 128){
            float a = 0.f;
            #pragma unroll 8
            for (int k = 0; k < C; k++)
                a = fmaf(__ldg(qw + k*C + t), __ldg(kb + k), a);
            g_v1[t] = a;
        } else {
            const int j = t - 128;
            float a = 0.f;
            #pragma unroll 8
            for (int k = 0; k < C; k++)
                a = fmaf(__ldg(qb + k), __ldg(kw + k*C + j), a);
            g_v2[j] = a;
        }
        if (t == 0){
            float g = 0.f;
            #pragma unroll 8
            for (int k = 0; k < C; k++) g = fmaf(__ldg(qb + k), __ldg(kb + k), g);
            g_gamma[0] = g;
        }
    }
}

// ---------------------------------------------------------------------------
// proj: u'[b][oc][px] = sum_ic x[ic][px]*M[ic][oc] + v2[oc]
// mma.sync bf16 hi/lo compensated GEMM (3 terms). CTA = 128px x 128oc x K=128.
// smem rows padded to 272B (68 words mod 32 = 4 -> ldmatrix conflict-free).
// ---------------------------------------------------------------------------
#define A_STRIDE 272                 // bytes per px row (128 bf16 data + pad)
#define TILE_BYTES (128 * A_STRIDE)  // 34816
#define AH_OFF 0
#define AL_OFF (TILE_BYTES)
#define BH_OFF (2*TILE_BYTES)
#define BL_OFF (3*TILE_BYTES)
#define PROJ_SMEM (4*TILE_BYTES)     // 139264 B

__global__ __launch_bounds__(256) void proj_kernel(const float* __restrict__ feat){
    extern __shared__ char sm[];
    const uint32_t smb = smem_u32(sm);
    const int tid  = threadIdx.x;
    const int lane = tid & 31;
    const int wid  = tid >> 5;
    const int b    = blockIdx.y;
    const int px0  = blockIdx.x * 128;

    // ---- stage B tiles: g_Mhi/g_Mlo [oc][ic] bf16 -> smem, 272B row stride
    {
        const float4* sh = (const float4*)g_Mhi;
        const float4* sl = (const float4*)g_Mlo;
        for (int e = tid; e < 2048; e += 256){
            int row = e >> 4, seg = e & 15;
            *(float4*)(sm + BH_OFF + row*A_STRIDE + seg*16) = sh[row*16 + seg];
            *(float4*)(sm + BL_OFF + row*A_STRIDE + seg*16) = sl[row*16 + seg];
        }
    }

    // ---- stage A tiles: transpose x[ic][px] -> bf16 [px][ic] hi/lo
    {
        const int px  = tid & 127;
        const int ich = (tid >> 7) * 64;
        const float* fp = feat + (size_t)(b*C + ich)*HW + px0 + px;
        char* ah = sm + AH_OFF + px*A_STRIDE + ich*2;
        char* al = sm + AL_OFF + px*A_STRIDE + ich*2;
        #pragma unroll 4
        for (int g = 0; g < 16; g++){
            float v0 = fp[(size_t)(g*4+0)*HW];
            float v1 = fp[(size_t)(g*4+1)*HW];
            float v2 = fp[(size_t)(g*4+2)*HW];
            float v3 = fp[(size_t)(g*4+3)*HW];
            unsigned short h0,h1,h2,h3,l0,l1,l2,l3;
            split_bf16(v0,h0,l0); split_bf16(v1,h1,l1);
            split_bf16(v2,h2,l2); split_bf16(v3,h3,l3);
            *(ull*)(ah + g*8) = (ull)h0 | ((ull)h1<<16) | ((ull)h2<<32) | ((ull)h3<<48);
            *(ull*)(al + g*8) = (ull)l0 | ((ull)l1<<16) | ((ull)l2<<32) | ((ull)l3<<48);
        }
    }
    __syncthreads();

    // ---- warp tiling: wy = px block (4 x 32), wx = oc block (2 x 64)
    const int wy = wid >> 1;
    const int wx = wid & 1;
    const int m_base = wy * 32;          // px offset within tile
    const int n_base = wx * 64;          // oc offset within tile

    float d[2][8][4];
    #pragma unroll
    for (int i = 0; i < 2; i++)
        #pragma unroll
        for (int j = 0; j < 8; j++)
            #pragma unroll
            for (int k = 0; k < 4; k++) d[i][j][k] = 0.f;

    // ldmatrix lane-address components
    const int a_sub = lane >> 3;                         // 0..3
    const int a_row_off = (a_sub & 1)*8 + (lane & 7);    // row within m16
    const int a_col_off = (a_sub >> 1)*8;                // col within k16
    const int b_row_off = (a_sub >> 1)*8 + (lane & 7);   // row within n16
    const int b_col_off = (a_sub & 1)*8;                 // col within k16

    #pragma unroll
    for (int term = 0; term < 3; term++){
        const uint32_t abase = smb + ((term == 2) ? AL_OFF : AH_OFF);
        const uint32_t bbase = smb + ((term == 1) ? BL_OFF : BH_OFF);
        #pragma unroll
        for (int ks = 0; ks < 8; ks++){
            const int k0 = ks * 16;
            uint32_t afr[2][4];
            #pragma unroll
            for (int mb = 0; mb < 2; mb++){
                uint32_t addr = abase + (m_base + mb*16 + a_row_off)*A_STRIDE
                                      + (k0 + a_col_off)*2;
                ldm_x4(addr, afr[mb][0], afr[mb][1], afr[mb][2], afr[mb][3]);
            }
            uint32_t bfr[8][2];
            #pragma unroll
            for (int nb2 = 0; nb2 < 4; nb2++){
                uint32_t addr = bbase + (n_base + nb2*16 + b_row_off)*A_STRIDE
                                      + (k0 + b_col_off)*2;
                uint32_t r0, r1, r2, r3;
                ldm_x4(addr, r0, r1, r2, r3);
                bfr[nb2*2][0]   = r0; bfr[nb2*2][1]   = r1;
                bfr[nb2*2+1][0] = r2; bfr[nb2*2+1][1] = r3;
            }
            #pragma unroll
            for (int mb = 0; mb < 2; mb++)
                #pragma unroll
                for (int nb = 0; nb < 8; nb++)
                    mma_bf16(d[mb][nb], afr[mb], bfr[nb]);
        }
    }

    // ---- epilogue: direct stores (each quad covers a full 32B sector) + v2
    {
        const int gid = lane >> 2;        // 0..7 -> px row
        const int tq  = lane & 3;         // 0..3 -> oc pair
        float* ub = g_U + (size_t)b*C*HW + px0;
        #pragma unroll
        for (int nb = 0; nb < 8; nb++){
            const int oc = n_base + nb*8 + tq*2;
            const float v2a = __ldg(g_v2 + oc);
            const float v2b = __ldg(g_v2 + oc + 1);
            float* r0 = ub + (size_t)oc * HW;
            float* r1 = ub + (size_t)(oc+1) * HW;
            #pragma unroll
            for (int mb = 0; mb < 2; mb++){
                const int px = m_base + mb*16 + gid;
                r0[px]     = d[mb][nb][0] + v2a;
                r1[px]     = d[mb][nb][1] + v2b;
                r0[px + 8] = d[mb][nb][2] + v2a;
                r1[px + 8] = d[mb][nb][3] + v2b;
            }
        }
    }
}

// ---------------------------------------------------------------------------
// attn: score_n = (u'.x_n + v1.x_p + gamma)/sqrt(C); OOB -> exactly 0;
// softmax over 9; weighted flow gather (OOB flow contributes 0).
// ---------------------------------------------------------------------------
__global__ __launch_bounds__(256) void attn_kernel(const float* __restrict__ feat,
                                                   const float* __restrict__ flow,
                                                   float* __restrict__ out){
    __shared__ float sK[8][ROWS+2][W+4];
    __shared__ float sV1[C];

    const int tid = threadIdx.x;
    const int b = blockIdx.y;
    const int rowBase = blockIdx.x * ROWS;
    const int r = tid >> 7;
    const int x = tid & 127;
    const int y = rowBase + r;
    const int p = y*W + x;

    for (int e = tid; e < C; e += 256) sV1[e] = g_v1[e];

    const float* ub = g_U + (size_t)b*C*HW + p;
    const float* fb = feat + (size_t)b*C*HW;

    float s[9];
    #pragma unroll
    for (int n = 0; n < 9; n++) s[n] = 0.f;
    float a = 0.f;

    for (int cb = 0; cb < C; cb += 8){
        for (int e = tid; e < 8*(ROWS+2)*130; e += 256){
            int c   = e / ((ROWS+2)*130);
            int rem = e - c*((ROWS+2)*130);
            int row = rem / 130;
            int col = rem - row*130;
            int gy = rowBase - 1 + row;
            int gx = col - 1;
            float v = 0.f;
            if ((unsigned)gy < (unsigned)H && (unsigned)gx < (unsigned)W)
                v = fb[(size_t)(cb + c)*HW + gy*W + gx];
            sK[c][row][col] = v;
        }
        __syncthreads();
        #pragma unroll
        for (int cc = 0; cc < 8; cc++){
            float uv = ub[(size_t)(cb + cc)*HW];
            float center = sK[cc][r+1][x+1];
            a = fmaf(sV1[cb + cc], center, a);
            #pragma unroll
            for (int dy = 0; dy < 3; dy++)
                #pragma unroll
                for (int dx = 0; dx < 3; dx++)
                    s[dy*3+dx] = fmaf(uv, sK[cc][r+dy][x+dx], s[dy*3+dx]);
        }
        __syncthreads();
    }

    const float alpha = a + g_gamma[0];
    const float INV = 0.08838834764831843f;   // 1/sqrt(128)

    float sc[9];
    #pragma unroll
    for (int dy = 0; dy < 3; dy++)
        #pragma unroll
        for (int dx = 0; dx < 3; dx++){
            int n = dy*3+dx;
            bool inb = ((unsigned)(y+dy-1) < (unsigned)H) &&
                       ((unsigned)(x+dx-1) < (unsigned)W);
            sc[n] = inb ? (s[n] + alpha) * INV : 0.f;
        }

    float m = sc[0];
    #pragma unroll
    for (int n = 1; n < 9; n++) m = fmaxf(m, sc[n]);
    float es[9], sum = 0.f;
    #pragma unroll
    for (int n = 0; n < 9; n++){ es[n] = __expf(sc[n] - m); sum += es[n]; }
    const float isum = 1.f / sum;

    const float* fl0 = flow + (size_t)(b*2)*HW;
    const float* fl1 = fl0 + HW;
    float f0 = 0.f, f1 = 0.f;
    #pragma unroll
    for (int dy = 0; dy < 3; dy++)
        #pragma unroll
        for (int dx = 0; dx < 3; dx++){
            int n = dy*3+dx;
            int gy = y + dy - 1, gx = x + dx - 1;
            if ((unsigned)gy < (unsigned)H && (unsigned)gx < (unsigned)W){
                int pn = gy*W + gx;
                float pr = es[n] * isum;
                f0 = fmaf(pr, fl0[pn], f0);
                f1 = fmaf(pr, fl1[pn], f1);
            }
        }
    out[(size_t)(b*2)*HW + p]   = f0;
    out[(size_t)(b*2+1)*HW + p] = f1;
}

extern "C" void kernel_launch(void* const* d_in, const int* in_sizes, int n_in,
                              void* d_out, int out_size){
    const float* feature0 = (const float*)d_in[0];
    const float* flow     = (const float*)d_in[1];
    const float* q_w      = (const float*)d_in[2];
    const float* q_b      = (const float*)d_in[3];
    const float* k_w      = (const float*)d_in[4];
    const float* k_b      = (const float*)d_in[5];
    float* out = (float*)d_out;
    (void)in_sizes; (void)n_in; (void)out_size;

    precomp_kernel<<<17, 256>>>(q_w, q_b, k_w, k_b);

    cudaFuncSetAttribute(proj_kernel, cudaFuncAttributeMaxDynamicSharedMemorySize, PROJ_SMEM);
    proj_kernel<<<dim3(HW/128, BB), 256, PROJ_SMEM>>>(feature0);

    attn_kernel<<<dim3(H/ROWS, BB), 256>>>(feature0, flow, out);
}